// round 4
// baseline (speedup 1.0000x reference)
#include <cuda_runtime.h>
#include <cuda_bf16.h>
#include <cstdint>

// Problem shape
#define MROWS   8192          // B*S
#define NOUT    8192
#define KIN     2048
#define KTILES  32            // KIN / 64
#define TILE_B  16384         // 128 rows * 128 bytes (64 bf16), SW128-swizzled

// Scratch (device globals: allocation-free rule)
__device__ unsigned       g_amax[2];                 // [0]=x, [1]=w (float bits)
__device__ __nv_bfloat16  g_xq[(size_t)MROWS * KIN]; // tiled+swizzled
__device__ __nv_bfloat16  g_wq[(size_t)NOUT * KIN];  // tiled+swizzled

#define SW128(o) ((o) ^ (((o) >> 3) & 0x70))

__device__ __forceinline__ uint32_t smem_u32(const void* p) {
    uint32_t a;
    asm("{ .reg .u64 t; cvta.to.shared.u64 t, %1; cvt.u32.u64 %0, t; }" : "=r"(a) : "l"(p));
    return a;
}

__device__ __forceinline__ void cp16(uint32_t dst, const void* src) {
    asm volatile("cp.async.cg.shared.global [%0], [%1], 16;" :: "r"(dst), "l"(src) : "memory");
}

__device__ __forceinline__ void ldsm_x4(uint32_t& r0, uint32_t& r1, uint32_t& r2, uint32_t& r3,
                                        uint32_t addr) {
    asm volatile("ldmatrix.sync.aligned.m8n8.x4.shared.b16 {%0,%1,%2,%3}, [%4];"
                 : "=r"(r0), "=r"(r1), "=r"(r2), "=r"(r3) : "r"(addr));
}

__device__ __forceinline__ void mma16816(float* c, const uint32_t* a, uint32_t b0, uint32_t b1) {
    asm volatile(
        "mma.sync.aligned.m16n8k16.row.col.f32.bf16.bf16.f32 "
        "{%0,%1,%2,%3}, {%4,%5,%6,%7}, {%8,%9}, {%0,%1,%2,%3};"
        : "+f"(c[0]), "+f"(c[1]), "+f"(c[2]), "+f"(c[3])
        : "r"(a[0]), "r"(a[1]), "r"(a[2]), "r"(a[3]), "r"(b0), "r"(b1));
}

// ---------------------------------------------------------------------------
__global__ void init_k() {
    if (threadIdx.x < 2) g_amax[threadIdx.x] = 0u;
}

// amax via float-bit max (abs values non-negative => bit compare == float compare)
__global__ void amax_k(const float4* __restrict__ src, int n4, int which) {
    unsigned m = 0;
    for (int i = blockIdx.x * blockDim.x + threadIdx.x; i < n4; i += gridDim.x * blockDim.x) {
        float4 v = src[i];
        m = max(m, __float_as_uint(fabsf(v.x)));
        m = max(m, __float_as_uint(fabsf(v.y)));
        m = max(m, __float_as_uint(fabsf(v.z)));
        m = max(m, __float_as_uint(fabsf(v.w)));
    }
    #pragma unroll
    for (int o = 16; o; o >>= 1) m = max(m, __shfl_xor_sync(0xFFFFFFFFu, m, o));
    if ((threadIdx.x & 31) == 0) atomicMax(&g_amax[which], m);
}

// Quantize into tiled + SW128-pre-swizzled bf16 layout.
// Tile = 128 rows x 64 k (16KB); tiles ordered [row/128][k/64].
__global__ void quant_k(const float* __restrict__ src, int which) {
    __nv_bfloat16* dst = which ? g_wq : g_xq;
    float scale = __uint_as_float(g_amax[which]) / 448.0f;
    int t = blockIdx.x * blockDim.x + threadIdx.x;
    if (t >= (MROWS * KIN / 8)) return;
    int row = t >> 8;
    int k   = (t & 255) << 3;
    const float4* s = (const float4*)(src + (size_t)row * KIN + k);
    float4 a = s[0], b = s[1];
    __align__(16) __nv_bfloat16 q[8];
    q[0] = __float2bfloat16(a.x / scale);
    q[1] = __float2bfloat16(a.y / scale);
    q[2] = __float2bfloat16(a.z / scale);
    q[3] = __float2bfloat16(a.w / scale);
    q[4] = __float2bfloat16(b.x / scale);
    q[5] = __float2bfloat16(b.y / scale);
    q[6] = __float2bfloat16(b.z / scale);
    q[7] = __float2bfloat16(b.w / scale);
    int rt = row >> 7, r = row & 127, kt = k >> 6, c = k & 63;
    size_t byte = (size_t)(rt * KTILES + kt) * TILE_B + SW128(r * 128 + c * 2);
    *(uint4*)((char*)dst + byte) = *(const uint4*)q;
}

// ---------------------------------------------------------------------------
// GEMM: CTA tile 128(M) x 256(N) x 64(K-chunk), 256 threads = 8 warps (2x4),
// warp tile 64x64, 4-stage cp.async pipeline + double-buffered ldmatrix frags.
#define STAGES   4
#define STAGE_B  49152          // 16KB A + 32KB B
#define SMEM_SZ  (STAGES * STAGE_B)

struct Frag { uint32_t a[4][4]; uint32_t b[4][4]; };

__device__ __forceinline__ void load_frags(uint32_t dA, uint32_t dB, int ks,
                                           int wm, int wn, int ra, int kha,
                                           int rb, int khb, Frag& f) {
    #pragma unroll
    for (int mt = 0; mt < 4; mt++) {
        uint32_t off = (uint32_t)(wm * 64 + mt * 16 + ra) * 128 + ks * 32 + kha;
        ldsm_x4(f.a[mt][0], f.a[mt][1], f.a[mt][2], f.a[mt][3], dA + SW128(off));
    }
    #pragma unroll
    for (int nt = 0; nt < 4; nt++) {
        int n = wn * 64 + nt * 16 + rb;
        uint32_t off = ((uint32_t)(n >> 7)) * 16384 +
                       SW128((uint32_t)(n & 127) * 128 + ks * 32 + khb);
        ldsm_x4(f.b[nt][0], f.b[nt][1], f.b[nt][2], f.b[nt][3], dB + off);
    }
}

__global__ void __launch_bounds__(256, 1)
gemm_k(const float* __restrict__ bias, float* __restrict__ out) {
    extern __shared__ __align__(1024) char smem[];
    const uint32_t sb = smem_u32(smem);
    const int tid = threadIdx.x, lane = tid & 31, wid = tid >> 5;
    const int wm = wid >> 2, wn = wid & 3;           // warp grid 2(M) x 4(N)
    const int mt_blk = blockIdx.y, nt_blk = blockIdx.x;

    const char* Ab = (const char*)g_xq + (size_t)(mt_blk * KTILES) * TILE_B;
    const char* B0 = (const char*)g_wq + (size_t)((2 * nt_blk)     * KTILES) * TILE_B;
    const char* B1 = (const char*)g_wq + (size_t)((2 * nt_blk + 1) * KTILES) * TILE_B;

    // stage copy: tiles are pre-swizzled, so this is a linear 48KB memcpy
    auto load_stage = [&](int kt, int s) {
        uint32_t d = sb + s * STAGE_B;
        size_t go = (size_t)kt * TILE_B;
        #pragma unroll
        for (int j = 0; j < 4; j++) {
            uint32_t off = tid * 16 + j * 4096;
            cp16(d + off,          Ab + go + off);
            cp16(d + 16384 + off,  B0 + go + off);
            cp16(d + 32768 + off,  B1 + go + off);
        }
        asm volatile("cp.async.commit_group;" ::: "memory");
    };

    // per-lane ldmatrix address components
    const int ra  = (lane & 7) + ((lane >> 3) & 1) * 8;   // A row within 16
    const int kha = (lane >> 4) * 16;                      // A k-half byte offset
    const int rb  = (lane & 7) + ((lane >> 4) & 1) * 8;   // B n within 16
    const int khb = ((lane >> 3) & 1) * 16;                // B k-half byte offset

    float acc[4][8][4];
    #pragma unroll
    for (int i = 0; i < 4; i++)
        #pragma unroll
        for (int j = 0; j < 8; j++)
            #pragma unroll
            for (int l = 0; l < 4; l++) acc[i][j][l] = 0.0f;

    load_stage(0, 0);
    load_stage(1, 1);
    load_stage(2, 2);
    load_stage(3, 3);

    Frag fr[2];

    for (int kt = 0; kt < KTILES; kt++) {
        asm volatile("cp.async.wait_group 3;" ::: "memory");
        __syncthreads();
        const int s = kt & (STAGES - 1);
        const uint32_t dA = sb + s * STAGE_B;
        const uint32_t dB = dA + 16384;

        load_frags(dA, dB, 0, wm, wn, ra, kha, rb, khb, fr[0]);

        #pragma unroll
        for (int ks = 0; ks < 4; ks++) {
            if (ks < 3)
                load_frags(dA, dB, ks + 1, wm, wn, ra, kha, rb, khb, fr[(ks + 1) & 1]);
            Frag& f = fr[ks & 1];
            #pragma unroll
            for (int mt = 0; mt < 4; mt++)
                #pragma unroll
                for (int nt = 0; nt < 4; nt++) {
                    mma16816(acc[mt][2 * nt],     f.a[mt], f.b[nt][0], f.b[nt][1]);
                    mma16816(acc[mt][2 * nt + 1], f.a[mt], f.b[nt][2], f.b[nt][3]);
                }
        }
        __syncthreads();
        if (kt + STAGES < KTILES) load_stage(kt + STAGES, s);
        else asm volatile("cp.async.commit_group;" ::: "memory");  // keep group count invariant
    }

    // epilogue: round accum to bf16 (match XLA bf16 einsum output), scale, +bias
    const float scale = (__uint_as_float(g_amax[0]) / 448.0f) *
                        (__uint_as_float(g_amax[1]) / 448.0f);
    const int g = lane >> 2, t4 = lane & 3;

    #pragma unroll
    for (int mt = 0; mt < 4; mt++) {
        size_t r0 = (size_t)mt_blk * 128 + wm * 64 + mt * 16 + g;
        size_t r1 = r0 + 8;
        #pragma unroll
        for (int n8 = 0; n8 < 8; n8++) {
            int col = nt_blk * 256 + wn * 64 + n8 * 8 + t4 * 2;
            float2 bv = *(const float2*)(bias + col);
            float2 o0, o1;
            o0.x = __bfloat162float(__float2bfloat16(acc[mt][n8][0])) * scale + bv.x;
            o0.y = __bfloat162float(__float2bfloat16(acc[mt][n8][1])) * scale + bv.y;
            o1.x = __bfloat162float(__float2bfloat16(acc[mt][n8][2])) * scale + bv.x;
            o1.y = __bfloat162float(__float2bfloat16(acc[mt][n8][3])) * scale + bv.y;
            __stcs((float2*)(out + r0 * NOUT + col), o0);
            __stcs((float2*)(out + r1 * NOUT + col), o1);
        }
    }
}

// ---------------------------------------------------------------------------
extern "C" void kernel_launch(void* const* d_in, const int* in_sizes, int n_in,
                              void* d_out, int out_size) {
    const float* x    = (const float*)d_in[0];   // [2,4096,2048]
    const float* w    = (const float*)d_in[1];   // [8192,2048]
    const float* bias = (const float*)d_in[2];   // [8192]
    float* out = (float*)d_out;
    (void)in_sizes; (void)n_in; (void)out_size;

    init_k<<<1, 32>>>();
    amax_k<<<1024, 256>>>((const float4*)x, MROWS * KIN / 4, 0);
    amax_k<<<1024, 256>>>((const float4*)w, NOUT * KIN / 4, 1);
    quant_k<<<8192, 256>>>(x, 0);
    quant_k<<<8192, 256>>>(w, 1);

    cudaFuncSetAttribute(gemm_k, cudaFuncAttributeMaxDynamicSharedMemorySize, SMEM_SZ);
    gemm_k<<<dim3(NOUT / 256, MROWS / 128, 1), 256, SMEM_SZ>>>(bias, out);
}

// round 5
// speedup vs baseline: 1.0229x; 1.0229x over previous
#include <cuda_runtime.h>
#include <cuda_bf16.h>
#include <cstdint>

// Problem shape
#define MROWS   8192          // B*S
#define NOUT    8192
#define KIN     2048
#define KTILES  32            // KIN / 64
#define TILE_B  16384         // 128 rows * 128 bytes (64 bf16), SW128-swizzled

// Scratch (device globals: allocation-free rule)
__device__ unsigned       g_amax[2];                 // [0]=x, [1]=w (float bits)
__device__ __nv_bfloat16  g_xq[(size_t)MROWS * KIN]; // tiled+swizzled
__device__ __nv_bfloat16  g_wq[(size_t)NOUT * KIN];  // tiled+swizzled

#define SW128(o) ((o) ^ (((o) >> 3) & 0x70))

__device__ __forceinline__ uint32_t smem_u32(const void* p) {
    uint32_t a;
    asm("{ .reg .u64 t; cvta.to.shared.u64 t, %1; cvt.u32.u64 %0, t; }" : "=r"(a) : "l"(p));
    return a;
}

__device__ __forceinline__ void cp16(uint32_t dst, const void* src) {
    asm volatile("cp.async.cg.shared.global [%0], [%1], 16;" :: "r"(dst), "l"(src) : "memory");
}

__device__ __forceinline__ void ldsm_x4(uint32_t& r0, uint32_t& r1, uint32_t& r2, uint32_t& r3,
                                        uint32_t addr) {
    asm volatile("ldmatrix.sync.aligned.m8n8.x4.shared.b16 {%0,%1,%2,%3}, [%4];"
                 : "=r"(r0), "=r"(r1), "=r"(r2), "=r"(r3) : "r"(addr));
}

__device__ __forceinline__ void mma16816(float* c, const uint32_t* a, uint32_t b0, uint32_t b1) {
    asm volatile(
        "mma.sync.aligned.m16n8k16.row.col.f32.bf16.bf16.f32 "
        "{%0,%1,%2,%3}, {%4,%5,%6,%7}, {%8,%9}, {%0,%1,%2,%3};"
        : "+f"(c[0]), "+f"(c[1]), "+f"(c[2]), "+f"(c[3])
        : "r"(a[0]), "r"(a[1]), "r"(a[2]), "r"(a[3]), "r"(b0), "r"(b1));
}

// ---------------------------------------------------------------------------
__global__ void init_k() {
    if (threadIdx.x < 2) g_amax[threadIdx.x] = 0u;
}

// amax via float-bit max (abs values non-negative => bit compare == float compare)
__global__ void amax_k(const float4* __restrict__ src, int n4, int which) {
    unsigned m = 0;
    for (int i = blockIdx.x * blockDim.x + threadIdx.x; i < n4; i += gridDim.x * blockDim.x) {
        float4 v = src[i];
        m = max(m, __float_as_uint(fabsf(v.x)));
        m = max(m, __float_as_uint(fabsf(v.y)));
        m = max(m, __float_as_uint(fabsf(v.z)));
        m = max(m, __float_as_uint(fabsf(v.w)));
    }
    #pragma unroll
    for (int o = 16; o; o >>= 1) m = max(m, __shfl_xor_sync(0xFFFFFFFFu, m, o));
    if ((threadIdx.x & 31) == 0) atomicMax(&g_amax[which], m);
}

// Quantize into tiled + SW128-pre-swizzled bf16 layout.
// Tile = 128 rows x 64 k (16KB); tiles ordered [row/128][k/64].
__global__ void quant_k(const float* __restrict__ src, int which) {
    __nv_bfloat16* dst = which ? g_wq : g_xq;
    float scale = __uint_as_float(g_amax[which]) / 448.0f;
    int t = blockIdx.x * blockDim.x + threadIdx.x;
    if (t >= (MROWS * KIN / 8)) return;
    int row = t >> 8;
    int k   = (t & 255) << 3;
    const float4* s = (const float4*)(src + (size_t)row * KIN + k);
    float4 a = s[0], b = s[1];
    __align__(16) __nv_bfloat16 q[8];
    q[0] = __float2bfloat16(a.x / scale);
    q[1] = __float2bfloat16(a.y / scale);
    q[2] = __float2bfloat16(a.z / scale);
    q[3] = __float2bfloat16(a.w / scale);
    q[4] = __float2bfloat16(b.x / scale);
    q[5] = __float2bfloat16(b.y / scale);
    q[6] = __float2bfloat16(b.z / scale);
    q[7] = __float2bfloat16(b.w / scale);
    int rt = row >> 7, r = row & 127, kt = k >> 6, c = k & 63;
    size_t byte = (size_t)(rt * KTILES + kt) * TILE_B + SW128(r * 128 + c * 2);
    *(uint4*)((char*)dst + byte) = *(const uint4*)q;
}

// ---------------------------------------------------------------------------
// GEMM: CTA tile 128(M) x 256(N) x 64(K-chunk), 512 threads = 16 warps (4x4),
// warp tile 32x64 -> 4 warps/SMSP. 4 smem slots, 3 copies in flight,
// single __syncthreads per kt.
#define STAGES   4
#define STAGE_B  49152          // 16KB A + 32KB B
#define SMEM_SZ  (STAGES * STAGE_B)

__global__ void __launch_bounds__(512, 1)
gemm_k(const float* __restrict__ bias, float* __restrict__ out) {
    extern __shared__ __align__(1024) char smem[];
    const uint32_t sb = smem_u32(smem);
    const int tid = threadIdx.x, lane = tid & 31, wid = tid >> 5;
    const int wm = wid >> 2, wn = wid & 3;           // warp grid 4(M) x 4(N)
    const int mt_blk = blockIdx.y, nt_blk = blockIdx.x;

    const char* Ab = (const char*)g_xq + (size_t)(mt_blk * KTILES) * TILE_B;
    const char* B0 = (const char*)g_wq + (size_t)((2 * nt_blk)     * KTILES) * TILE_B;
    const char* B1 = (const char*)g_wq + (size_t)((2 * nt_blk + 1) * KTILES) * TILE_B;

    // stage copy: tiles pre-swizzled => linear 48KB memcpy; 96B per thread
    auto load_stage = [&](int kt, int s) {
        uint32_t d = sb + s * STAGE_B;
        size_t go = (size_t)kt * TILE_B;
        #pragma unroll
        for (int j = 0; j < 2; j++) {
            uint32_t off = tid * 16 + j * 8192;
            cp16(d + off,          Ab + go + off);
            cp16(d + 16384 + off,  B0 + go + off);
            cp16(d + 32768 + off,  B1 + go + off);
        }
        asm volatile("cp.async.commit_group;" ::: "memory");
    };

    // per-lane ldmatrix address components
    const int ra  = (lane & 7) + ((lane >> 3) & 1) * 8;   // A row within 16
    const int kha = (lane >> 4) * 16;                      // A k-half byte offset
    const int rb  = (lane & 7) + ((lane >> 4) & 1) * 8;   // B n within 16
    const int khb = ((lane >> 3) & 1) * 16;                // B k-half byte offset

    float acc[2][8][4];
    #pragma unroll
    for (int i = 0; i < 2; i++)
        #pragma unroll
        for (int j = 0; j < 8; j++)
            #pragma unroll
            for (int l = 0; l < 4; l++) acc[i][j][l] = 0.0f;

    load_stage(0, 0);
    load_stage(1, 1);
    load_stage(2, 2);

    for (int kt = 0; kt < KTILES; kt++) {
        // 3 copy groups in flight (kt, kt+1, kt+2): wait until stage kt landed
        asm volatile("cp.async.wait_group 2;" ::: "memory");
        __syncthreads();
        // refill the slot consumed last iteration ((kt-1)&3 == (kt+3)&3);
        // all warps are past the barrier, so no one still reads it
        if (kt + 3 < KTILES) load_stage(kt + 3, (kt + 3) & (STAGES - 1));
        else asm volatile("cp.async.commit_group;" ::: "memory");  // keep group count invariant

        const uint32_t dA = sb + (kt & (STAGES - 1)) * STAGE_B;
        const uint32_t dB = dA + 16384;

        #pragma unroll
        for (int ks = 0; ks < 4; ks++) {
            uint32_t a[2][4];
            #pragma unroll
            for (int mt = 0; mt < 2; mt++) {
                uint32_t off = (uint32_t)(wm * 32 + mt * 16 + ra) * 128 + ks * 32 + kha;
                ldsm_x4(a[mt][0], a[mt][1], a[mt][2], a[mt][3], dA + SW128(off));
            }
            uint32_t b[4][4];
            #pragma unroll
            for (int nt = 0; nt < 4; nt++) {
                int n = wn * 64 + nt * 16 + rb;
                uint32_t off = ((uint32_t)(n >> 7)) * 16384 +
                               SW128((uint32_t)(n & 127) * 128 + ks * 32 + khb);
                ldsm_x4(b[nt][0], b[nt][1], b[nt][2], b[nt][3], dB + off);
            }
            #pragma unroll
            for (int mt = 0; mt < 2; mt++)
                #pragma unroll
                for (int nt = 0; nt < 4; nt++) {
                    mma16816(acc[mt][2 * nt],     a[mt], b[nt][0], b[nt][1]);
                    mma16816(acc[mt][2 * nt + 1], a[mt], b[nt][2], b[nt][3]);
                }
        }
    }

    // epilogue: round accum to bf16 (match XLA bf16 einsum output), scale, +bias
    const float scale = (__uint_as_float(g_amax[0]) / 448.0f) *
                        (__uint_as_float(g_amax[1]) / 448.0f);
    const int g = lane >> 2, t4 = lane & 3;

    #pragma unroll
    for (int mt = 0; mt < 2; mt++) {
        size_t r0 = (size_t)mt_blk * 128 + wm * 32 + mt * 16 + g;
        size_t r1 = r0 + 8;
        #pragma unroll
        for (int n8 = 0; n8 < 8; n8++) {
            int col = nt_blk * 256 + wn * 64 + n8 * 8 + t4 * 2;
            float2 bv = *(const float2*)(bias + col);
            float2 o0, o1;
            o0.x = __bfloat162float(__float2bfloat16(acc[mt][n8][0])) * scale + bv.x;
            o0.y = __bfloat162float(__float2bfloat16(acc[mt][n8][1])) * scale + bv.y;
            o1.x = __bfloat162float(__float2bfloat16(acc[mt][n8][2])) * scale + bv.x;
            o1.y = __bfloat162float(__float2bfloat16(acc[mt][n8][3])) * scale + bv.y;
            __stcs((float2*)(out + r0 * NOUT + col), o0);
            __stcs((float2*)(out + r1 * NOUT + col), o1);
        }
    }
}

// ---------------------------------------------------------------------------
extern "C" void kernel_launch(void* const* d_in, const int* in_sizes, int n_in,
                              void* d_out, int out_size) {
    const float* x    = (const float*)d_in[0];   // [2,4096,2048]
    const float* w    = (const float*)d_in[1];   // [8192,2048]
    const float* bias = (const float*)d_in[2];   // [8192]
    float* out = (float*)d_out;
    (void)in_sizes; (void)n_in; (void)out_size;

    init_k<<<1, 32>>>();
    amax_k<<<1024, 256>>>((const float4*)x, MROWS * KIN / 4, 0);
    amax_k<<<1024, 256>>>((const float4*)w, NOUT * KIN / 4, 1);
    quant_k<<<8192, 256>>>(x, 0);
    quant_k<<<8192, 256>>>(w, 1);

    cudaFuncSetAttribute(gemm_k, cudaFuncAttributeMaxDynamicSharedMemorySize, SMEM_SZ);
    gemm_k<<<dim3(NOUT / 256, MROWS / 128, 1), 512, SMEM_SZ>>>(bias, out);
}

// round 6
// speedup vs baseline: 1.0303x; 1.0072x over previous
#include <cuda_runtime.h>
#include <cuda_bf16.h>
#include <cstdint>

// Problem shape
#define MROWS   8192          // B*S
#define NOUT    8192
#define KIN     2048
#define KTILES  32            // KIN / 64
#define TILE_B  16384         // 128 rows * 128 bytes (64 bf16), SW128-swizzled

// Scratch (device globals: allocation-free rule)
__device__ unsigned       g_amax[2];                 // [0]=x, [1]=w (float bits)
__device__ __nv_bfloat16  g_xq[(size_t)MROWS * KIN]; // tiled+swizzled
__device__ __nv_bfloat16  g_wq[(size_t)NOUT * KIN];  // tiled+swizzled

#define SW128(o) ((o) ^ (((o) >> 3) & 0x70))

__device__ __forceinline__ uint32_t smem_u32(const void* p) {
    uint32_t a;
    asm("{ .reg .u64 t; cvta.to.shared.u64 t, %1; cvt.u32.u64 %0, t; }" : "=r"(a) : "l"(p));
    return a;
}

__device__ __forceinline__ void cp16(uint32_t dst, const void* src) {
    asm volatile("cp.async.cg.shared.global [%0], [%1], 16;" :: "r"(dst), "l"(src) : "memory");
}

__device__ __forceinline__ void ldsm_x4(uint32_t& r0, uint32_t& r1, uint32_t& r2, uint32_t& r3,
                                        uint32_t addr) {
    asm volatile("ldmatrix.sync.aligned.m8n8.x4.shared.b16 {%0,%1,%2,%3}, [%4];"
                 : "=r"(r0), "=r"(r1), "=r"(r2), "=r"(r3) : "r"(addr));
}

__device__ __forceinline__ void mma16816(float* c, const uint32_t* a, uint32_t b0, uint32_t b1) {
    asm volatile(
        "mma.sync.aligned.m16n8k16.row.col.f32.bf16.bf16.f32 "
        "{%0,%1,%2,%3}, {%4,%5,%6,%7}, {%8,%9}, {%0,%1,%2,%3};"
        : "+f"(c[0]), "+f"(c[1]), "+f"(c[2]), "+f"(c[3])
        : "r"(a[0]), "r"(a[1]), "r"(a[2]), "r"(a[3]), "r"(b0), "r"(b1));
}

// ---------------------------------------------------------------------------
__global__ void init_k() {
    if (threadIdx.x < 2) g_amax[threadIdx.x] = 0u;
}

// amax for BOTH tensors in one launch (blockIdx.y selects). Bit-max == float
// max on non-negative floats.
__global__ void amax2_k(const float4* __restrict__ x, const float4* __restrict__ w, int n4) {
    const float4* src = blockIdx.y ? w : x;
    unsigned m = 0;
    for (int i = blockIdx.x * blockDim.x + threadIdx.x; i < n4; i += gridDim.x * blockDim.x) {
        float4 v = src[i];
        m = max(m, __float_as_uint(fabsf(v.x)));
        m = max(m, __float_as_uint(fabsf(v.y)));
        m = max(m, __float_as_uint(fabsf(v.z)));
        m = max(m, __float_as_uint(fabsf(v.w)));
    }
    #pragma unroll
    for (int o = 16; o; o >>= 1) m = max(m, __shfl_xor_sync(0xFFFFFFFFu, m, o));
    if ((threadIdx.x & 31) == 0) atomicMax(&g_amax[blockIdx.y], m);
}

// Quantize into tiled + SW128-pre-swizzled bf16 layout; 2 chunks per thread.
__global__ void quant_k(const float* __restrict__ src, int which) {
    __nv_bfloat16* dst = which ? g_wq : g_xq;
    float inv = 448.0f / __uint_as_float(g_amax[which]);  // multiply ~= divide here? NO:
    // reference does v / scale with scale = amax/448; v/scale != v*inv in fp.
    float scale = __uint_as_float(g_amax[which]) / 448.0f;
    (void)inv;
    int t0 = blockIdx.x * blockDim.x + threadIdx.x;
    #pragma unroll
    for (int it = 0; it < 2; it++) {
        int t = t0 + it * (MROWS * KIN / 16);      // two halves of the tensor
        int row = t >> 8;
        int k   = (t & 255) << 3;
        const float4* s = (const float4*)(src + (size_t)row * KIN + k);
        float4 a = s[0], b = s[1];
        __align__(16) __nv_bfloat16 q[8];
        q[0] = __float2bfloat16(a.x / scale);
        q[1] = __float2bfloat16(a.y / scale);
        q[2] = __float2bfloat16(a.z / scale);
        q[3] = __float2bfloat16(a.w / scale);
        q[4] = __float2bfloat16(b.x / scale);
        q[5] = __float2bfloat16(b.y / scale);
        q[6] = __float2bfloat16(b.z / scale);
        q[7] = __float2bfloat16(b.w / scale);
        int rt = row >> 7, r = row & 127, kt = k >> 6, c = k & 63;
        size_t byte = (size_t)(rt * KTILES + kt) * TILE_B + SW128(r * 128 + c * 2);
        *(uint4*)((char*)dst + byte) = *(const uint4*)q;
    }
}

// ---------------------------------------------------------------------------
// GEMM: CTA tile 128(M) x 256(N) x 64(K-chunk), 512 threads = 16 warps (4x4),
// warp tile 32x64 -> 4 warps/SMSP. 4 smem slots, 3 copies in flight,
// single __syncthreads per kt.
#define STAGES   4
#define STAGE_B  49152          // 16KB A + 32KB B
#define SMEM_SZ  (STAGES * STAGE_B)

__global__ void __launch_bounds__(512, 1)
gemm_k(const float* __restrict__ bias, float* __restrict__ out) {
    extern __shared__ __align__(1024) char smem[];
    const uint32_t sb = smem_u32(smem);
    const int tid = threadIdx.x, lane = tid & 31, wid = tid >> 5;
    const int wm = wid >> 2, wn = wid & 3;           // warp grid 4(M) x 4(N)
    const int mt_blk = blockIdx.y, nt_blk = blockIdx.x;

    const char* Ab = (const char*)g_xq + (size_t)(mt_blk * KTILES) * TILE_B;
    const char* B0 = (const char*)g_wq + (size_t)((2 * nt_blk)     * KTILES) * TILE_B;
    const char* B1 = (const char*)g_wq + (size_t)((2 * nt_blk + 1) * KTILES) * TILE_B;

    // stage copy: tiles pre-swizzled => linear 48KB memcpy; 96B per thread
    auto load_stage = [&](int kt, int s) {
        uint32_t d = sb + s * STAGE_B;
        size_t go = (size_t)kt * TILE_B;
        #pragma unroll
        for (int j = 0; j < 2; j++) {
            uint32_t off = tid * 16 + j * 8192;
            cp16(d + off,          Ab + go + off);
            cp16(d + 16384 + off,  B0 + go + off);
            cp16(d + 32768 + off,  B1 + go + off);
        }
        asm volatile("cp.async.commit_group;" ::: "memory");
    };

    // per-lane ldmatrix address components
    const int ra  = (lane & 7) + ((lane >> 3) & 1) * 8;   // A row within 16
    const int kha = (lane >> 4) * 16;                      // A k-half byte offset
    const int rb  = (lane & 7) + ((lane >> 4) & 1) * 8;   // B n within 16
    const int khb = ((lane >> 3) & 1) * 16;                // B k-half byte offset

    float acc[2][8][4];
    #pragma unroll
    for (int i = 0; i < 2; i++)
        #pragma unroll
        for (int j = 0; j < 8; j++)
            #pragma unroll
            for (int l = 0; l < 4; l++) acc[i][j][l] = 0.0f;

    load_stage(0, 0);
    load_stage(1, 1);
    load_stage(2, 2);

    for (int kt = 0; kt < KTILES; kt++) {
        // 3 copy groups in flight (kt, kt+1, kt+2): wait until stage kt landed
        asm volatile("cp.async.wait_group 2;" ::: "memory");
        __syncthreads();
        // refill the slot consumed last iteration ((kt-1)&3 == (kt+3)&3)
        if (kt + 3 < KTILES) load_stage(kt + 3, (kt + 3) & (STAGES - 1));
        else asm volatile("cp.async.commit_group;" ::: "memory");  // keep group count invariant

        const uint32_t dA = sb + (kt & (STAGES - 1)) * STAGE_B;
        const uint32_t dB = dA + 16384;

        #pragma unroll
        for (int ks = 0; ks < 4; ks++) {
            uint32_t a[2][4];
            #pragma unroll
            for (int mt = 0; mt < 2; mt++) {
                uint32_t off = (uint32_t)(wm * 32 + mt * 16 + ra) * 128 + ks * 32 + kha;
                ldsm_x4(a[mt][0], a[mt][1], a[mt][2], a[mt][3], dA + SW128(off));
            }
            uint32_t b[4][4];
            #pragma unroll
            for (int nt = 0; nt < 4; nt++) {
                int n = wn * 64 + nt * 16 + rb;
                uint32_t off = ((uint32_t)(n >> 7)) * 16384 +
                               SW128((uint32_t)(n & 127) * 128 + ks * 32 + khb);
                ldsm_x4(b[nt][0], b[nt][1], b[nt][2], b[nt][3], dB + off);
            }
            #pragma unroll
            for (int mt = 0; mt < 2; mt++)
                #pragma unroll
                for (int nt = 0; nt < 4; nt++) {
                    mma16816(acc[mt][2 * nt],     a[mt], b[nt][0], b[nt][1]);
                    mma16816(acc[mt][2 * nt + 1], a[mt], b[nt][2], b[nt][3]);
                }
        }
    }

    // epilogue: round accum to bf16 (match XLA bf16 einsum output), scale, +bias
    const float scale = (__uint_as_float(g_amax[0]) / 448.0f) *
                        (__uint_as_float(g_amax[1]) / 448.0f);
    const int g = lane >> 2, t4 = lane & 3;

    #pragma unroll
    for (int mt = 0; mt < 2; mt++) {
        size_t r0 = (size_t)mt_blk * 128 + wm * 32 + mt * 16 + g;
        size_t r1 = r0 + 8;
        #pragma unroll
        for (int n8 = 0; n8 < 8; n8++) {
            int col = nt_blk * 256 + wn * 64 + n8 * 8 + t4 * 2;
            float2 bv = *(const float2*)(bias + col);
            float2 o0, o1;
            o0.x = __bfloat162float(__float2bfloat16(acc[mt][n8][0])) * scale + bv.x;
            o0.y = __bfloat162float(__float2bfloat16(acc[mt][n8][1])) * scale + bv.y;
            o1.x = __bfloat162float(__float2bfloat16(acc[mt][n8][2])) * scale + bv.x;
            o1.y = __bfloat162float(__float2bfloat16(acc[mt][n8][3])) * scale + bv.y;
            __stcs((float2*)(out + r0 * NOUT + col), o0);
            __stcs((float2*)(out + r1 * NOUT + col), o1);
        }
    }
}

// ---------------------------------------------------------------------------
extern "C" void kernel_launch(void* const* d_in, const int* in_sizes, int n_in,
                              void* d_out, int out_size) {
    const float* x    = (const float*)d_in[0];   // [2,4096,2048]
    const float* w    = (const float*)d_in[1];   // [8192,2048]
    const float* bias = (const float*)d_in[2];   // [8192]
    float* out = (float*)d_out;
    (void)in_sizes; (void)n_in; (void)out_size;

    init_k<<<1, 32>>>();
    amax2_k<<<dim3(512, 2), 256>>>((const float4*)x, (const float4*)w, MROWS * KIN / 4);
    quant_k<<<4096, 256>>>(x, 0);
    quant_k<<<4096, 256>>>(w, 1);

    cudaFuncSetAttribute(gemm_k, cudaFuncAttributeMaxDynamicSharedMemorySize, SMEM_SZ);
    gemm_k<<<dim3(NOUT / 256, MROWS / 128, 1), 512, SMEM_SZ>>>(bias, out);
}